// round 1
// baseline (speedup 1.0000x reference)
#include <cuda_runtime.h>
#include <math.h>

// ---------------------------------------------------------------------------
// FourierEmbedding: N=131072 rows, D=4, F=64 (fin=129), H=128.
// Per d: feat[64x129] @ w1[d][129x128] -> LN -> ReLU -> @ w2[d][128x128],
// summed over d; then LN -> ReLU -> @ w3[128x128].
// One CTA = 64 rows, 256 threads. Thread tile: 4 rows x 8 cols, accumulated
// as packed f32x2 pairs via Blackwell fma.rn.f32x2 (2 FLOP / fma-pipe slot).
// Weights streamed through smem per-d; feat/h tile in smem; LN via shfl.
// ---------------------------------------------------------------------------

#define ULL unsigned long long

static __device__ __forceinline__ ULL pack2(float lo, float hi) {
    ULL r;
    asm("mov.b64 %0, {%1,%2};" : "=l"(r) : "f"(lo), "f"(hi));
    return r;
}
static __device__ __forceinline__ float2 unpack2(ULL v) {
    float lo, hi;
    asm("mov.b64 {%0,%1}, %2;" : "=f"(lo), "=f"(hi) : "l"(v));
    return make_float2(lo, hi);
}
static __device__ __forceinline__ ULL fma2(ULL a, ULL b, ULL c) {
    ULL d;
    asm("fma.rn.f32x2 %0, %1, %2, %3;" : "=l"(d) : "l"(a), "l"(b), "l"(c));
    return d;
}
static __device__ __forceinline__ ULL add2(ULL a, ULL b) {
    ULL d;
    asm("add.rn.f32x2 %0, %1, %2;" : "=l"(d) : "l"(a), "l"(b));
    return d;
}

static constexpr int NROWS   = 131072;
static constexpr int D       = 4;
static constexpr int F       = 64;
static constexpr int FIN     = 129;   // 2F + 1
static constexpr int H       = 128;
static constexpr int TM      = 64;    // rows per CTA
static constexpr int FS      = 132;   // feat/h row stride in smem (16B-aligned, odd/4)
static constexpr int THREADS = 256;

// smem: s_feat [TM][FS]  +  s_w [FIN][H]
static constexpr int SMEM_FLOATS = TM * FS + FIN * H;          // 8448 + 16512
static constexpr int SMEM_BYTES  = SMEM_FLOATS * 4;            // 99840 B

// GEMM over K=128 (multiple of 4): sA is [row][FS] row-major tile,
// sW is [k][H] row-major. acc pairs are along columns: acc[r][p] covers
// cols (c0+2p, c0+2p+1).
static __device__ __forceinline__ void gemm128(
    const float* __restrict__ sA, const float* __restrict__ sW,
    int r0, int c0, ULL acc[4][4])
{
#pragma unroll 1
    for (int k0 = 0; k0 < 128; k0 += 4) {
        float4 fa[4];
#pragma unroll
        for (int r = 0; r < 4; ++r)
            fa[r] = *reinterpret_cast<const float4*>(sA + (r0 + r) * FS + k0);
#pragma unroll
        for (int kk = 0; kk < 4; ++kk) {
            const ulonglong2 wv0 =
                *reinterpret_cast<const ulonglong2*>(sW + (k0 + kk) * H + c0);
            const ulonglong2 wv1 =
                *reinterpret_cast<const ulonglong2*>(sW + (k0 + kk) * H + c0 + 4);
#pragma unroll
            for (int r = 0; r < 4; ++r) {
                const float f = reinterpret_cast<const float*>(&fa[r])[kk];
                const ULL fd = pack2(f, f);
                acc[r][0] = fma2(fd, wv0.x, acc[r][0]);
                acc[r][1] = fma2(fd, wv0.y, acc[r][1]);
                acc[r][2] = fma2(fd, wv1.x, acc[r][2]);
                acc[r][3] = fma2(fd, wv1.y, acc[r][3]);
            }
        }
    }
}

__global__ __launch_bounds__(THREADS, 2)
void fourier_embedding_kernel(
    const float* __restrict__ cont,   // [N, 4]
    const float* __restrict__ freqs,  // [4, 64]
    const float* __restrict__ w1,     // [4, 129, 128]
    const float* __restrict__ b1,     // [4, 128]
    const float* __restrict__ ln1g,   // [4, 128]
    const float* __restrict__ ln1b,   // [4, 128]
    const float* __restrict__ w2,     // [4, 128, 128]
    const float* __restrict__ b2,     // [4, 128]
    const float* __restrict__ outg,   // [128]
    const float* __restrict__ outb,   // [128]
    const float* __restrict__ w3,     // [128, 128]
    const float* __restrict__ b3,     // [128]
    float* __restrict__ out)          // [N, 128]
{
    extern __shared__ float smem[];
    float* s_feat = smem;              // [TM][FS]
    float* s_w    = smem + TM * FS;    // [FIN][H]

    const int tid  = threadIdx.x;
    const int tx   = tid & 15;         // column group (16)
    const int ty   = tid >> 4;         // row group (16)
    const int r0   = ty << 2;          // 4 rows per thread
    const int c0   = tx << 3;          // 8 cols per thread
    const int row0 = blockIdx.x * TM;

    ULL accE[4][4];                    // emb accumulator (pairs over cols)
#pragma unroll
    for (int r = 0; r < 4; ++r)
#pragma unroll
        for (int p = 0; p < 4; ++p) accE[r][p] = 0ull;

    for (int d = 0; d < D; ++d) {
        __syncthreads();   // protect s_feat / s_w reuse from previous iter

        // ---- Fourier features -> s_feat[row][0..128] ----
        {
            const int fr = tid >> 2;            // row 0..63 (4 threads/row)
            const int fb = (tid & 3) << 4;      // freq base 0/16/32/48
            const float x = cont[(row0 + fr) * D + d];
            float* dst = s_feat + fr * FS;
#pragma unroll
            for (int j = 0; j < 16; ++j) {
                const float ang = x * freqs[(d << 6) + fb + j] * 6.283185307179586477f;
                float sv, cv;
                sincosf(ang, &sv, &cv);
                dst[fb + j]      = cv;   // cos block [0,64)
                dst[F + fb + j]  = sv;   // sin block [64,128)
            }
            if ((tid & 3) == 0) dst[2 * F] = x;  // raw input at index 128
        }
        // ---- stage w1[d] (129x128) into s_w ----
        {
            const float4* src = reinterpret_cast<const float4*>(w1 + d * FIN * H);
            float4* dst = reinterpret_cast<float4*>(s_w);
            for (int i = tid; i < (FIN * H) / 4; i += THREADS) dst[i] = src[i];
        }
        __syncthreads();

        // ---- GEMM1: feat @ w1 ----
        ULL acc1[4][4];
#pragma unroll
        for (int r = 0; r < 4; ++r)
#pragma unroll
            for (int p = 0; p < 4; ++p) acc1[r][p] = 0ull;
        gemm128(s_feat, s_w, r0, c0, acc1);
        {   // k = 128 tail (the raw-x feature)
            const ulonglong2 wv0 =
                *reinterpret_cast<const ulonglong2*>(s_w + 128 * H + c0);
            const ulonglong2 wv1 =
                *reinterpret_cast<const ulonglong2*>(s_w + 128 * H + c0 + 4);
#pragma unroll
            for (int r = 0; r < 4; ++r) {
                const float f = s_feat[(r0 + r) * FS + 128];
                const ULL fd = pack2(f, f);
                acc1[r][0] = fma2(fd, wv0.x, acc1[r][0]);
                acc1[r][1] = fma2(fd, wv0.y, acc1[r][1]);
                acc1[r][2] = fma2(fd, wv1.x, acc1[r][2]);
                acc1[r][3] = fma2(fd, wv1.y, acc1[r][3]);
            }
        }
        __syncthreads();   // everyone done reading s_feat / s_w

        // ---- bias + LayerNorm + ReLU -> store h into s_feat[row][0..127] ----
        {
            float gv[8], bv[8], biasv[8];
#pragma unroll
            for (int i = 0; i < 8; ++i) {
                gv[i]    = ln1g[(d << 7) + c0 + i];
                bv[i]    = ln1b[(d << 7) + c0 + i];
                biasv[i] = b1[(d << 7) + c0 + i];
            }
#pragma unroll
            for (int r = 0; r < 4; ++r) {
                float h[8];
#pragma unroll
                for (int p = 0; p < 4; ++p) {
                    const float2 t = unpack2(acc1[r][p]);
                    h[2 * p]     = t.x + biasv[2 * p];
                    h[2 * p + 1] = t.y + biasv[2 * p + 1];
                }
                float sum = 0.f, sq = 0.f;
#pragma unroll
                for (int i = 0; i < 8; ++i) { sum += h[i]; sq += h[i] * h[i]; }
#pragma unroll
                for (int m = 8; m >= 1; m >>= 1) {
                    sum += __shfl_xor_sync(0xffffffffu, sum, m);
                    sq  += __shfl_xor_sync(0xffffffffu, sq,  m);
                }
                const float mu  = sum * (1.0f / 128.0f);
                const float var = sq * (1.0f / 128.0f) - mu * mu;
                const float rs  = rsqrtf(var + 1e-5f);
                float* hd = s_feat + (r0 + r) * FS + c0;
#pragma unroll
                for (int i = 0; i < 8; ++i) {
                    const float v = (h[i] - mu) * rs * gv[i] + bv[i];
                    hd[i] = fmaxf(v, 0.0f);
                }
            }
        }
        // ---- stage w2[d] (128x128) into s_w ----
        {
            const float4* src = reinterpret_cast<const float4*>(w2 + d * H * H);
            float4* dst = reinterpret_cast<float4*>(s_w);
            for (int i = tid; i < (H * H) / 4; i += THREADS) dst[i] = src[i];
        }
        __syncthreads();

        // ---- GEMM2: h @ w2 (+ b2), accumulate into emb ----
        ULL acc2[4][4];
        {
            ULL binit[4];
#pragma unroll
            for (int p = 0; p < 4; ++p)
                binit[p] = pack2(b2[(d << 7) + c0 + 2 * p],
                                 b2[(d << 7) + c0 + 2 * p + 1]);
#pragma unroll
            for (int r = 0; r < 4; ++r)
#pragma unroll
                for (int p = 0; p < 4; ++p) acc2[r][p] = binit[p];
        }
        gemm128(s_feat, s_w, r0, c0, acc2);
#pragma unroll
        for (int r = 0; r < 4; ++r)
#pragma unroll
            for (int p = 0; p < 4; ++p) accE[r][p] = add2(accE[r][p], acc2[r][p]);
    }

    __syncthreads();

    // ---- out LayerNorm + ReLU -> s_feat ----
    {
        float gv[8], bv[8];
#pragma unroll
        for (int i = 0; i < 8; ++i) { gv[i] = outg[c0 + i]; bv[i] = outb[c0 + i]; }
#pragma unroll
        for (int r = 0; r < 4; ++r) {
            float e[8];
#pragma unroll
            for (int p = 0; p < 4; ++p) {
                const float2 t = unpack2(accE[r][p]);
                e[2 * p] = t.x; e[2 * p + 1] = t.y;
            }
            float sum = 0.f, sq = 0.f;
#pragma unroll
            for (int i = 0; i < 8; ++i) { sum += e[i]; sq += e[i] * e[i]; }
#pragma unroll
            for (int m = 8; m >= 1; m >>= 1) {
                sum += __shfl_xor_sync(0xffffffffu, sum, m);
                sq  += __shfl_xor_sync(0xffffffffu, sq,  m);
            }
            const float mu  = sum * (1.0f / 128.0f);
            const float var = sq * (1.0f / 128.0f) - mu * mu;
            const float rs  = rsqrtf(var + 1e-5f);
            float* ed = s_feat + (r0 + r) * FS + c0;
#pragma unroll
            for (int i = 0; i < 8; ++i) {
                const float v = (e[i] - mu) * rs * gv[i] + bv[i];
                ed[i] = fmaxf(v, 0.0f);
            }
        }
    }
    // ---- stage w3 into s_w ----
    {
        const float4* src = reinterpret_cast<const float4*>(w3);
        float4* dst = reinterpret_cast<float4*>(s_w);
        for (int i = tid; i < (H * H) / 4; i += THREADS) dst[i] = src[i];
    }
    __syncthreads();

    // ---- GEMM3: emb @ w3 (+ b3) -> out ----
    ULL acc3[4][4];
    {
        ULL binit[4];
#pragma unroll
        for (int p = 0; p < 4; ++p)
            binit[p] = pack2(b3[c0 + 2 * p], b3[c0 + 2 * p + 1]);
#pragma unroll
        for (int r = 0; r < 4; ++r)
#pragma unroll
            for (int p = 0; p < 4; ++p) acc3[r][p] = binit[p];
    }
    gemm128(s_feat, s_w, r0, c0, acc3);

#pragma unroll
    for (int r = 0; r < 4; ++r) {
        float o[8];
#pragma unroll
        for (int p = 0; p < 4; ++p) {
            const float2 t = unpack2(acc3[r][p]);
            o[2 * p] = t.x; o[2 * p + 1] = t.y;
        }
        float4* op = reinterpret_cast<float4*>(out + (row0 + r0 + r) * H + c0);
        op[0] = make_float4(o[0], o[1], o[2], o[3]);
        op[1] = make_float4(o[4], o[5], o[6], o[7]);
    }
}

extern "C" void kernel_launch(void* const* d_in, const int* in_sizes, int n_in,
                              void* d_out, int out_size)
{
    const float* cont  = (const float*)d_in[0];
    const float* freqs = (const float*)d_in[1];
    const float* w1    = (const float*)d_in[2];
    const float* b1    = (const float*)d_in[3];
    const float* ln1g  = (const float*)d_in[4];
    const float* ln1b  = (const float*)d_in[5];
    const float* w2    = (const float*)d_in[6];
    const float* b2    = (const float*)d_in[7];
    const float* outg  = (const float*)d_in[8];
    const float* outb  = (const float*)d_in[9];
    const float* w3    = (const float*)d_in[10];
    const float* b3    = (const float*)d_in[11];
    float* out = (float*)d_out;

    cudaFuncSetAttribute(fourier_embedding_kernel,
                         cudaFuncAttributeMaxDynamicSharedMemorySize, SMEM_BYTES);

    fourier_embedding_kernel<<<NROWS / TM, THREADS, SMEM_BYTES>>>(
        cont, freqs, w1, b1, ln1g, ln1b, w2, b2, outg, outb, w3, b3, out);
}

// round 2
// speedup vs baseline: 1.0001x; 1.0001x over previous
#include <cuda_runtime.h>
#include <math.h>

// ---------------------------------------------------------------------------
// FourierEmbedding: N=131072 rows, D=4, F=64 (fin=129), H=128.
// Per d: feat[64x129] @ w1[d][129x128] -> LN -> ReLU -> @ w2[d][128x128],
// summed over d; then LN -> ReLU -> @ w3[128x128].
// One CTA = 64 rows, 256 threads. Thread tile: 4 rows x 8 cols, accumulated
// as packed f32x2 pairs via Blackwell fma.rn.f32x2 (2 FLOP / fma-pipe slot).
// Weights streamed through smem per-d; feat/h tile in smem; LN via shfl.
// ---------------------------------------------------------------------------

#define ULL unsigned long long

static __device__ __forceinline__ ULL pack2(float lo, float hi) {
    ULL r;
    asm("mov.b64 %0, {%1,%2};" : "=l"(r) : "f"(lo), "f"(hi));
    return r;
}
static __device__ __forceinline__ float2 unpack2(ULL v) {
    float lo, hi;
    asm("mov.b64 {%0,%1}, %2;" : "=f"(lo), "=f"(hi) : "l"(v));
    return make_float2(lo, hi);
}
static __device__ __forceinline__ ULL fma2(ULL a, ULL b, ULL c) {
    ULL d;
    asm("fma.rn.f32x2 %0, %1, %2, %3;" : "=l"(d) : "l"(a), "l"(b), "l"(c));
    return d;
}
static __device__ __forceinline__ ULL add2(ULL a, ULL b) {
    ULL d;
    asm("add.rn.f32x2 %0, %1, %2;" : "=l"(d) : "l"(a), "l"(b));
    return d;
}

static constexpr int NROWS   = 131072;
static constexpr int D       = 4;
static constexpr int F       = 64;
static constexpr int FIN     = 129;   // 2F + 1
static constexpr int H       = 128;
static constexpr int TM      = 64;    // rows per CTA
static constexpr int FS      = 132;   // feat/h row stride in smem (16B-aligned, odd/4)
static constexpr int THREADS = 256;

// smem: s_feat [TM][FS]  +  s_w [FIN][H]
static constexpr int SMEM_FLOATS = TM * FS + FIN * H;          // 8448 + 16512
static constexpr int SMEM_BYTES  = SMEM_FLOATS * 4;            // 99840 B

// GEMM over K=128 (multiple of 4): sA is [row][FS] row-major tile,
// sW is [k][H] row-major. acc pairs are along columns: acc[r][p] covers
// cols (c0+2p, c0+2p+1).
static __device__ __forceinline__ void gemm128(
    const float* __restrict__ sA, const float* __restrict__ sW,
    int r0, int c0, ULL acc[4][4])
{
#pragma unroll 1
    for (int k0 = 0; k0 < 128; k0 += 4) {
        float4 fa[4];
#pragma unroll
        for (int r = 0; r < 4; ++r)
            fa[r] = *reinterpret_cast<const float4*>(sA + (r0 + r) * FS + k0);
#pragma unroll
        for (int kk = 0; kk < 4; ++kk) {
            const ulonglong2 wv0 =
                *reinterpret_cast<const ulonglong2*>(sW + (k0 + kk) * H + c0);
            const ulonglong2 wv1 =
                *reinterpret_cast<const ulonglong2*>(sW + (k0 + kk) * H + c0 + 4);
#pragma unroll
            for (int r = 0; r < 4; ++r) {
                const float f = reinterpret_cast<const float*>(&fa[r])[kk];
                const ULL fd = pack2(f, f);
                acc[r][0] = fma2(fd, wv0.x, acc[r][0]);
                acc[r][1] = fma2(fd, wv0.y, acc[r][1]);
                acc[r][2] = fma2(fd, wv1.x, acc[r][2]);
                acc[r][3] = fma2(fd, wv1.y, acc[r][3]);
            }
        }
    }
}

__global__ __launch_bounds__(THREADS, 2)
void fourier_embedding_kernel(
    const float* __restrict__ cont,   // [N, 4]
    const float* __restrict__ freqs,  // [4, 64]
    const float* __restrict__ w1,     // [4, 129, 128]
    const float* __restrict__ b1,     // [4, 128]
    const float* __restrict__ ln1g,   // [4, 128]
    const float* __restrict__ ln1b,   // [4, 128]
    const float* __restrict__ w2,     // [4, 128, 128]
    const float* __restrict__ b2,     // [4, 128]
    const float* __restrict__ outg,   // [128]
    const float* __restrict__ outb,   // [128]
    const float* __restrict__ w3,     // [128, 128]
    const float* __restrict__ b3,     // [128]
    float* __restrict__ out)          // [N, 128]
{
    extern __shared__ float smem[];
    float* s_feat = smem;              // [TM][FS]
    float* s_w    = smem + TM * FS;    // [FIN][H]

    const int tid  = threadIdx.x;
    const int tx   = tid & 15;         // column group (16)
    const int ty   = tid >> 4;         // row group (16)
    const int r0   = ty << 2;          // 4 rows per thread
    const int c0   = tx << 3;          // 8 cols per thread
    const int row0 = blockIdx.x * TM;

    ULL accE[4][4];                    // emb accumulator (pairs over cols)
#pragma unroll
    for (int r = 0; r < 4; ++r)
#pragma unroll
        for (int p = 0; p < 4; ++p) accE[r][p] = 0ull;

    for (int d = 0; d < D; ++d) {
        __syncthreads();   // protect s_feat / s_w reuse from previous iter

        // ---- Fourier features -> s_feat[row][0..128] ----
        {
            const int fr = tid >> 2;            // row 0..63 (4 threads/row)
            const int fb = (tid & 3) << 4;      // freq base 0/16/32/48
            const float x = cont[(row0 + fr) * D + d];
            float* dst = s_feat + fr * FS;
#pragma unroll
            for (int j = 0; j < 16; ++j) {
                const float ang = x * freqs[(d << 6) + fb + j] * 6.283185307179586477f;
                float sv, cv;
                sincosf(ang, &sv, &cv);
                dst[fb + j]      = cv;   // cos block [0,64)
                dst[F + fb + j]  = sv;   // sin block [64,128)
            }
            if ((tid & 3) == 0) dst[2 * F] = x;  // raw input at index 128
        }
        // ---- stage w1[d] (129x128) into s_w ----
        {
            const float4* src = reinterpret_cast<const float4*>(w1 + d * FIN * H);
            float4* dst = reinterpret_cast<float4*>(s_w);
            for (int i = tid; i < (FIN * H) / 4; i += THREADS) dst[i] = src[i];
        }
        __syncthreads();

        // ---- GEMM1: feat @ w1 ----
        ULL acc1[4][4];
#pragma unroll
        for (int r = 0; r < 4; ++r)
#pragma unroll
            for (int p = 0; p < 4; ++p) acc1[r][p] = 0ull;
        gemm128(s_feat, s_w, r0, c0, acc1);
        {   // k = 128 tail (the raw-x feature)
            const ulonglong2 wv0 =
                *reinterpret_cast<const ulonglong2*>(s_w + 128 * H + c0);
            const ulonglong2 wv1 =
                *reinterpret_cast<const ulonglong2*>(s_w + 128 * H + c0 + 4);
#pragma unroll
            for (int r = 0; r < 4; ++r) {
                const float f = s_feat[(r0 + r) * FS + 128];
                const ULL fd = pack2(f, f);
                acc1[r][0] = fma2(fd, wv0.x, acc1[r][0]);
                acc1[r][1] = fma2(fd, wv0.y, acc1[r][1]);
                acc1[r][2] = fma2(fd, wv1.x, acc1[r][2]);
                acc1[r][3] = fma2(fd, wv1.y, acc1[r][3]);
            }
        }
        __syncthreads();   // everyone done reading s_feat / s_w

        // ---- bias + LayerNorm + ReLU -> store h into s_feat[row][0..127] ----
        {
            float gv[8], bv[8], biasv[8];
#pragma unroll
            for (int i = 0; i < 8; ++i) {
                gv[i]    = ln1g[(d << 7) + c0 + i];
                bv[i]    = ln1b[(d << 7) + c0 + i];
                biasv[i] = b1[(d << 7) + c0 + i];
            }
#pragma unroll
            for (int r = 0; r < 4; ++r) {
                float h[8];
#pragma unroll
                for (int p = 0; p < 4; ++p) {
                    const float2 t = unpack2(acc1[r][p]);
                    h[2 * p]     = t.x + biasv[2 * p];
                    h[2 * p + 1] = t.y + biasv[2 * p + 1];
                }
                float sum = 0.f, sq = 0.f;
#pragma unroll
                for (int i = 0; i < 8; ++i) { sum += h[i]; sq += h[i] * h[i]; }
#pragma unroll
                for (int m = 8; m >= 1; m >>= 1) {
                    sum += __shfl_xor_sync(0xffffffffu, sum, m);
                    sq  += __shfl_xor_sync(0xffffffffu, sq,  m);
                }
                const float mu  = sum * (1.0f / 128.0f);
                const float var = sq * (1.0f / 128.0f) - mu * mu;
                const float rs  = rsqrtf(var + 1e-5f);
                float* hd = s_feat + (r0 + r) * FS + c0;
#pragma unroll
                for (int i = 0; i < 8; ++i) {
                    const float v = (h[i] - mu) * rs * gv[i] + bv[i];
                    hd[i] = fmaxf(v, 0.0f);
                }
            }
        }
        // ---- stage w2[d] (128x128) into s_w ----
        {
            const float4* src = reinterpret_cast<const float4*>(w2 + d * H * H);
            float4* dst = reinterpret_cast<float4*>(s_w);
            for (int i = tid; i < (H * H) / 4; i += THREADS) dst[i] = src[i];
        }
        __syncthreads();

        // ---- GEMM2: h @ w2 (+ b2), accumulate into emb ----
        ULL acc2[4][4];
        {
            ULL binit[4];
#pragma unroll
            for (int p = 0; p < 4; ++p)
                binit[p] = pack2(b2[(d << 7) + c0 + 2 * p],
                                 b2[(d << 7) + c0 + 2 * p + 1]);
#pragma unroll
            for (int r = 0; r < 4; ++r)
#pragma unroll
                for (int p = 0; p < 4; ++p) acc2[r][p] = binit[p];
        }
        gemm128(s_feat, s_w, r0, c0, acc2);
#pragma unroll
        for (int r = 0; r < 4; ++r)
#pragma unroll
            for (int p = 0; p < 4; ++p) accE[r][p] = add2(accE[r][p], acc2[r][p]);
    }

    __syncthreads();

    // ---- out LayerNorm + ReLU -> s_feat ----
    {
        float gv[8], bv[8];
#pragma unroll
        for (int i = 0; i < 8; ++i) { gv[i] = outg[c0 + i]; bv[i] = outb[c0 + i]; }
#pragma unroll
        for (int r = 0; r < 4; ++r) {
            float e[8];
#pragma unroll
            for (int p = 0; p < 4; ++p) {
                const float2 t = unpack2(accE[r][p]);
                e[2 * p] = t.x; e[2 * p + 1] = t.y;
            }
            float sum = 0.f, sq = 0.f;
#pragma unroll
            for (int i = 0; i < 8; ++i) { sum += e[i]; sq += e[i] * e[i]; }
#pragma unroll
            for (int m = 8; m >= 1; m >>= 1) {
                sum += __shfl_xor_sync(0xffffffffu, sum, m);
                sq  += __shfl_xor_sync(0xffffffffu, sq,  m);
            }
            const float mu  = sum * (1.0f / 128.0f);
            const float var = sq * (1.0f / 128.0f) - mu * mu;
            const float rs  = rsqrtf(var + 1e-5f);
            float* ed = s_feat + (r0 + r) * FS + c0;
#pragma unroll
            for (int i = 0; i < 8; ++i) {
                const float v = (e[i] - mu) * rs * gv[i] + bv[i];
                ed[i] = fmaxf(v, 0.0f);
            }
        }
    }
    // ---- stage w3 into s_w ----
    {
        const float4* src = reinterpret_cast<const float4*>(w3);
        float4* dst = reinterpret_cast<float4*>(s_w);
        for (int i = tid; i < (H * H) / 4; i += THREADS) dst[i] = src[i];
    }
    __syncthreads();

    // ---- GEMM3: emb @ w3 (+ b3) -> out ----
    ULL acc3[4][4];
    {
        ULL binit[4];
#pragma unroll
        for (int p = 0; p < 4; ++p)
            binit[p] = pack2(b3[c0 + 2 * p], b3[c0 + 2 * p + 1]);
#pragma unroll
        for (int r = 0; r < 4; ++r)
#pragma unroll
            for (int p = 0; p < 4; ++p) acc3[r][p] = binit[p];
    }
    gemm128(s_feat, s_w, r0, c0, acc3);

#pragma unroll
    for (int r = 0; r < 4; ++r) {
        float o[8];
#pragma unroll
        for (int p = 0; p < 4; ++p) {
            const float2 t = unpack2(acc3[r][p]);
            o[2 * p] = t.x; o[2 * p + 1] = t.y;
        }
        float4* op = reinterpret_cast<float4*>(out + (row0 + r0 + r) * H + c0);
        op[0] = make_float4(o[0], o[1], o[2], o[3]);
        op[1] = make_float4(o[4], o[5], o[6], o[7]);
    }
}

extern "C" void kernel_launch(void* const* d_in, const int* in_sizes, int n_in,
                              void* d_out, int out_size)
{
    const float* cont  = (const float*)d_in[0];
    const float* freqs = (const float*)d_in[1];
    const float* w1    = (const float*)d_in[2];
    const float* b1    = (const float*)d_in[3];
    const float* ln1g  = (const float*)d_in[4];
    const float* ln1b  = (const float*)d_in[5];
    const float* w2    = (const float*)d_in[6];
    const float* b2    = (const float*)d_in[7];
    const float* outg  = (const float*)d_in[8];
    const float* outb  = (const float*)d_in[9];
    const float* w3    = (const float*)d_in[10];
    const float* b3    = (const float*)d_in[11];
    float* out = (float*)d_out;

    cudaFuncSetAttribute(fourier_embedding_kernel,
                         cudaFuncAttributeMaxDynamicSharedMemorySize, SMEM_BYTES);

    fourier_embedding_kernel<<<NROWS / TM, THREADS, SMEM_BYTES>>>(
        cont, freqs, w1, b1, ln1g, ln1b, w2, b2, outg, outb, w3, b3, out);
}

// round 3
// speedup vs baseline: 1.5670x; 1.5668x over previous
#include <cuda_runtime.h>
#include <math.h>

// ---------------------------------------------------------------------------
// FourierEmbedding, R2: smem-wavefront fix.
// CTA = 64 rows x 128 cols, 256 threads. Thread tile: 8 rows x 4 cols.
// ty = warp id (8 rows per warp, broadcast activation loads, warp-local LN),
// tx = lane (4 cols). Packed fma.rn.f32x2 accumulators.
// Per 4-k chunk/warp: 8 bcast LDS + 4x4-wf weight LDS = 24 wf vs 64 FFMA2.
// ---------------------------------------------------------------------------

#define ULL unsigned long long

static __device__ __forceinline__ ULL pack2(float lo, float hi) {
    ULL r;
    asm("mov.b64 %0, {%1,%2};" : "=l"(r) : "f"(lo), "f"(hi));
    return r;
}
static __device__ __forceinline__ float2 unpack2(ULL v) {
    float lo, hi;
    asm("mov.b64 {%0,%1}, %2;" : "=f"(lo), "=f"(hi) : "l"(v));
    return make_float2(lo, hi);
}
static __device__ __forceinline__ ULL fma2(ULL a, ULL b, ULL c) {
    ULL d;
    asm("fma.rn.f32x2 %0, %1, %2, %3;" : "=l"(d) : "l"(a), "l"(b), "l"(c));
    return d;
}

static constexpr int NROWS   = 131072;
static constexpr int D       = 4;
static constexpr int F       = 64;
static constexpr int FIN     = 129;   // 2F + 1
static constexpr int H       = 128;
static constexpr int TM      = 64;    // rows per CTA
static constexpr int FS      = 132;   // feat/h row stride (16B aligned)
static constexpr int THREADS = 256;

// smem: s_feat [TM][FS] + s_w [FIN][H]
static constexpr int SMEM_FLOATS = TM * FS + FIN * H;   // 8448 + 16512
static constexpr int SMEM_BYTES  = SMEM_FLOATS * 4;     // 99840 B -> 2 CTAs/SM

// K=128 GEMM. sA [row][FS], sW [k][H]. acc[r][p] covers cols (c0+2p, c0+2p+1).
static __device__ __forceinline__ void gemm128(
    const float* __restrict__ sA, const float* __restrict__ sW,
    int r0, int c0, ULL acc[8][2])
{
#pragma unroll 1
    for (int k0 = 0; k0 < 128; k0 += 4) {
        float4 fa[8];
#pragma unroll
        for (int r = 0; r < 8; ++r)
            fa[r] = *reinterpret_cast<const float4*>(sA + (r0 + r) * FS + k0);
#pragma unroll
        for (int kk = 0; kk < 4; ++kk) {
            const ulonglong2 wv =
                *reinterpret_cast<const ulonglong2*>(sW + (k0 + kk) * H + c0);
#pragma unroll
            for (int r = 0; r < 8; ++r) {
                const float f = reinterpret_cast<const float*>(&fa[r])[kk];
                const ULL fd = pack2(f, f);
                acc[r][0] = fma2(fd, wv.x, acc[r][0]);
                acc[r][1] = fma2(fd, wv.y, acc[r][1]);
            }
        }
    }
}

__global__ __launch_bounds__(THREADS, 2)
void fourier_embedding_kernel(
    const float* __restrict__ cont,   // [N, 4]
    const float* __restrict__ freqs,  // [4, 64]
    const float* __restrict__ w1,     // [4, 129, 128]
    const float* __restrict__ b1,     // [4, 128]
    const float* __restrict__ ln1g,   // [4, 128]
    const float* __restrict__ ln1b,   // [4, 128]
    const float* __restrict__ w2,     // [4, 128, 128]
    const float* __restrict__ b2,     // [4, 128]
    const float* __restrict__ outg,   // [128]
    const float* __restrict__ outb,   // [128]
    const float* __restrict__ w3,     // [128, 128]
    const float* __restrict__ b3,     // [128]
    float* __restrict__ out)          // [N, 128]
{
    extern __shared__ float smem[];
    float* s_feat = smem;              // [TM][FS]
    float* s_w    = smem + TM * FS;    // [FIN][H]

    const int tid  = threadIdx.x;
    const int tx   = tid & 31;         // lane -> column group (32 x 4 cols)
    const int ty   = tid >> 5;         // warp -> row group (8 x 8 rows)
    const int r0   = ty << 3;
    const int c0   = tx << 2;
    const int row0 = blockIdx.x * TM;

    // emb accumulator, pre-initialized with sum_d b2[d]
    ULL accE[8][2];
    {
        float s0 = 0.f, s1 = 0.f, s2 = 0.f, s3 = 0.f;
#pragma unroll
        for (int d = 0; d < D; ++d) {
            s0 += b2[(d << 7) + c0 + 0];
            s1 += b2[(d << 7) + c0 + 1];
            s2 += b2[(d << 7) + c0 + 2];
            s3 += b2[(d << 7) + c0 + 3];
        }
        const ULL i0 = pack2(s0, s1), i1 = pack2(s2, s3);
#pragma unroll
        for (int r = 0; r < 8; ++r) { accE[r][0] = i0; accE[r][1] = i1; }
    }

#pragma unroll 1
    for (int d = 0; d < D; ++d) {
        __syncthreads();   // s_feat / s_w reuse from previous iteration

        // ---- Fourier features -> s_feat[row][0..128] ----
        {
            const int fr = tid >> 2;            // row 0..63 (4 threads/row)
            const int fb = (tid & 3) << 4;      // freq base 0/16/32/48
            const float x = cont[(row0 + fr) * D + d];
            float* dst = s_feat + fr * FS;
#pragma unroll
            for (int j = 0; j < 16; ++j) {
                const float ang = x * freqs[(d << 6) + fb + j] * 6.283185307179586477f;
                float sv, cv;
                __sincosf(ang, &sv, &cv);
                dst[fb + j]     = cv;   // cos block [0,64)
                dst[F + fb + j] = sv;   // sin block [64,128)
            }
            if ((tid & 3) == 0) dst[2 * F] = x; // raw input at index 128
        }
        // ---- stage w1[d] into s_w ----
        {
            const float4* src = reinterpret_cast<const float4*>(w1 + d * FIN * H);
            float4* dst = reinterpret_cast<float4*>(s_w);
            for (int i = tid; i < (FIN * H) / 4; i += THREADS) dst[i] = src[i];
        }
        __syncthreads();

        // ---- GEMM1: feat @ w1 ----
        ULL acc1[8][2];
#pragma unroll
        for (int r = 0; r < 8; ++r) { acc1[r][0] = 0ull; acc1[r][1] = 0ull; }
        gemm128(s_feat, s_w, r0, c0, acc1);
        {   // k = 128 tail (raw-x feature)
            const ulonglong2 wv =
                *reinterpret_cast<const ulonglong2*>(s_w + 128 * H + c0);
#pragma unroll
            for (int r = 0; r < 8; ++r) {
                const float f = s_feat[(r0 + r) * FS + 128];
                const ULL fd = pack2(f, f);
                acc1[r][0] = fma2(fd, wv.x, acc1[r][0]);
                acc1[r][1] = fma2(fd, wv.y, acc1[r][1]);
            }
        }

        // ---- bias + LN + ReLU -> h back to s_feat (warp owns its 8 rows) ----
        {
            float gv[4], bv[4], biasv[4];
#pragma unroll
            for (int i = 0; i < 4; ++i) {
                gv[i]    = ln1g[(d << 7) + c0 + i];
                bv[i]    = ln1b[(d << 7) + c0 + i];
                biasv[i] = b1[(d << 7) + c0 + i];
            }
#pragma unroll
            for (int r = 0; r < 8; ++r) {
                float h[4];
                const float2 t0 = unpack2(acc1[r][0]);
                const float2 t1 = unpack2(acc1[r][1]);
                h[0] = t0.x + biasv[0]; h[1] = t0.y + biasv[1];
                h[2] = t1.x + biasv[2]; h[3] = t1.y + biasv[3];
                float sum = 0.f, sq = 0.f;
#pragma unroll
                for (int i = 0; i < 4; ++i) { sum += h[i]; sq += h[i] * h[i]; }
#pragma unroll
                for (int m = 16; m >= 1; m >>= 1) {
                    sum += __shfl_xor_sync(0xffffffffu, sum, m);
                    sq  += __shfl_xor_sync(0xffffffffu, sq,  m);
                }
                const float mu  = sum * (1.0f / 128.0f);
                const float var = sq * (1.0f / 128.0f) - mu * mu;
                const float rs  = rsqrtf(var + 1e-5f);
                float* hd = s_feat + (r0 + r) * FS + c0;
#pragma unroll
                for (int i = 0; i < 4; ++i)
                    hd[i] = fmaxf((h[i] - mu) * rs * gv[i] + bv[i], 0.0f);
            }
        }
        __syncthreads();   // all GEMM1 s_w reads done, LN writes visible

        // ---- stage w2[d] into s_w ----
        {
            const float4* src = reinterpret_cast<const float4*>(w2 + d * H * H);
            float4* dst = reinterpret_cast<float4*>(s_w);
            for (int i = tid; i < (H * H) / 4; i += THREADS) dst[i] = src[i];
        }
        __syncthreads();

        // ---- GEMM2: h @ w2, accumulate directly into accE ----
        gemm128(s_feat, s_w, r0, c0, accE);
    }

    __syncthreads();

    // ---- out LayerNorm + ReLU -> s_feat ----
    {
        float gv[4], bv[4];
#pragma unroll
        for (int i = 0; i < 4; ++i) { gv[i] = outg[c0 + i]; bv[i] = outb[c0 + i]; }
#pragma unroll
        for (int r = 0; r < 8; ++r) {
            float e[4];
            const float2 t0 = unpack2(accE[r][0]);
            const float2 t1 = unpack2(accE[r][1]);
            e[0] = t0.x; e[1] = t0.y; e[2] = t1.x; e[3] = t1.y;
            float sum = 0.f, sq = 0.f;
#pragma unroll
            for (int i = 0; i < 4; ++i) { sum += e[i]; sq += e[i] * e[i]; }
#pragma unroll
            for (int m = 16; m >= 1; m >>= 1) {
                sum += __shfl_xor_sync(0xffffffffu, sum, m);
                sq  += __shfl_xor_sync(0xffffffffu, sq,  m);
            }
            const float mu  = sum * (1.0f / 128.0f);
            const float var = sq * (1.0f / 128.0f) - mu * mu;
            const float rs  = rsqrtf(var + 1e-5f);
            float* ed = s_feat + (r0 + r) * FS + c0;
#pragma unroll
            for (int i = 0; i < 4; ++i)
                ed[i] = fmaxf((e[i] - mu) * rs * gv[i] + bv[i], 0.0f);
        }
    }
    // ---- stage w3 into s_w ----
    {
        const float4* src = reinterpret_cast<const float4*>(w3);
        float4* dst = reinterpret_cast<float4*>(s_w);
        for (int i = tid; i < (H * H) / 4; i += THREADS) dst[i] = src[i];
    }
    __syncthreads();

    // ---- GEMM3: emb @ w3 (+ b3) -> out ----
    ULL acc3[8][2];
    {
        const ULL i0 = pack2(b3[c0 + 0], b3[c0 + 1]);
        const ULL i1 = pack2(b3[c0 + 2], b3[c0 + 3]);
#pragma unroll
        for (int r = 0; r < 8; ++r) { acc3[r][0] = i0; acc3[r][1] = i1; }
    }
    gemm128(s_feat, s_w, r0, c0, acc3);

#pragma unroll
    for (int r = 0; r < 8; ++r) {
        const float2 t0 = unpack2(acc3[r][0]);
        const float2 t1 = unpack2(acc3[r][1]);
        *reinterpret_cast<float4*>(out + (row0 + r0 + r) * H + c0) =
            make_float4(t0.x, t0.y, t1.x, t1.y);
    }
}

extern "C" void kernel_launch(void* const* d_in, const int* in_sizes, int n_in,
                              void* d_out, int out_size)
{
    const float* cont  = (const float*)d_in[0];
    const float* freqs = (const float*)d_in[1];
    const float* w1    = (const float*)d_in[2];
    const float* b1    = (const float*)d_in[3];
    const float* ln1g  = (const float*)d_in[4];
    const float* ln1b  = (const float*)d_in[5];
    const float* w2    = (const float*)d_in[6];
    const float* b2    = (const float*)d_in[7];
    const float* outg  = (const float*)d_in[8];
    const float* outb  = (const float*)d_in[9];
    const float* w3    = (const float*)d_in[10];
    const float* b3    = (const float*)d_in[11];
    float* out = (float*)d_out;

    cudaFuncSetAttribute(fourier_embedding_kernel,
                         cudaFuncAttributeMaxDynamicSharedMemorySize, SMEM_BYTES);

    fourier_embedding_kernel<<<NROWS / TM, THREADS, SMEM_BYTES>>>(
        cont, freqs, w1, b1, ln1g, ln1b, w2, b2, outg, outb, w3, b3, out);
}

// round 5
// speedup vs baseline: 4.0566x; 2.5887x over previous
#include <cuda_runtime.h>
#include <stdint.h>

// ============================================================================
// FourierEmbedding via warp-level bf16 mma.sync (m16n8k16), 3-term hi/lo split
// for fp32-grade accuracy. No tcgen05 (harness PTX target is compute_103).
//
// CTA = 64 rows, 256 threads = 8 warps in a 4(row) x 2(col) grid;
// warp tile = 16 rows x 64 cols. Per d:
//   featgen (bf16 hi/lo -> s_A) || cp.async w1-image -> s_B
//   GEMM1 (3 bf16 terms, K=128) -> regs
//   epi1: + x*w1[128,:] + b1, LN, ReLU -> bf16 hi/lo -> s_A  || cp.async w2
//   GEMM2 -> accE (accumulated over d, fp32)
// then LN(outg,outb)+ReLU -> s_A, GEMM3 (w3), +b3 -> out.
// Weight images pre-built once per launch: [n][k] row-major, hi bf16 at
// k*2, lo bf16 at 256+k*2, row stride 528 B (conflict-free ldmatrix).
// ============================================================================

static constexpr int NROWS   = 131072;
static constexpr int TM      = 64;
static constexpr int THREADS = 256;
static constexpr int RS      = 528;               // image row stride (bytes)
static constexpr int IMG     = 128 * RS;          // 67584 B per weight image
static constexpr int SA      = 0;                 // A image: 64 rows
static constexpr int SB      = TM * RS;           // 33792
static constexpr int REDO    = SB + IMG;          // 101376
static constexpr int SMEM_BYTES = REDO + 2 * 64 * 8;  // 102400 -> 2 CTA/SM

__device__ __align__(16) unsigned char g_wimg[9 * IMG];

// ---------------------------------------------------------------------------
static __device__ __forceinline__ uint32_t smem_u32(const void* p) {
    uint32_t a;
    asm("{ .reg .u64 t; cvta.to.shared.u64 t, %1; cvt.u32.u64 %0, t; }"
        : "=r"(a) : "l"(p));
    return a;
}
// packs: upper half = bf16(b), lower half = bf16(a)
static __device__ __forceinline__ uint32_t cvt_bf16x2(float b, float a) {
    uint32_t r;
    asm("cvt.rn.bf16x2.f32 %0, %1, %2;" : "=r"(r) : "f"(b), "f"(a));
    return r;
}
static __device__ __forceinline__ void pack_hilo(float a, float b,
                                                 uint32_t& hi, uint32_t& lo) {
    hi = cvt_bf16x2(b, a);
    const float ra = a - __uint_as_float(hi << 16);
    const float rb = b - __uint_as_float(hi & 0xffff0000u);
    lo = cvt_bf16x2(rb, ra);
}
static __device__ __forceinline__ void cp_async16(uint32_t dst, const void* src) {
    asm volatile("cp.async.cg.shared.global [%0], [%1], 16;"
                 :: "r"(dst), "l"(src) : "memory");
}
#define CP_COMMIT() asm volatile("cp.async.commit_group;" ::: "memory")
#define CP_WAIT0()  asm volatile("cp.async.wait_group 0;" ::: "memory")

static __device__ __forceinline__ void ldsm4(uint32_t (&r)[4], uint32_t addr) {
    asm volatile("ldmatrix.sync.aligned.m8n8.x4.shared.b16 {%0,%1,%2,%3}, [%4];"
        : "=r"(r[0]), "=r"(r[1]), "=r"(r[2]), "=r"(r[3]) : "r"(addr));
}
static __device__ __forceinline__ void mma16816(float* c, const uint32_t* a,
                                                uint32_t b0, uint32_t b1) {
    asm volatile(
        "mma.sync.aligned.m16n8k16.row.col.f32.bf16.bf16.f32 "
        "{%0,%1,%2,%3},{%4,%5,%6,%7},{%8,%9},{%0,%1,%2,%3};"
        : "+f"(c[0]), "+f"(c[1]), "+f"(c[2]), "+f"(c[3])
        : "r"(a[0]), "r"(a[1]), "r"(a[2]), "r"(a[3]), "r"(b0), "r"(b1));
}

// K=128, 3-term bf16 GEMM into acc[8][4] (8 n-tiles of m16n8).
static __device__ __forceinline__ void gemm_bf16x3(uint32_t aBase, uint32_t bBase,
                                                   float (&acc)[8][4]) {
#pragma unroll 1
    for (int ks = 0; ks < 8; ++ks) {
        const uint32_t kb = (uint32_t)ks * 32u;
        uint32_t ah[4], al[4];
        ldsm4(ah, aBase + kb);
        ldsm4(al, aBase + kb + 256u);
#pragma unroll
        for (int np = 0; np < 4; ++np) {
            uint32_t bh[4], bl[4];
            const uint32_t bAddr = bBase + (uint32_t)np * (16u * RS) + kb;
            ldsm4(bh, bAddr);
            ldsm4(bl, bAddr + 256u);
            mma16816(acc[2 * np],     ah, bh[0], bh[1]);
            mma16816(acc[2 * np + 1], ah, bh[2], bh[3]);
            mma16816(acc[2 * np],     al, bh[0], bh[1]);
            mma16816(acc[2 * np + 1], al, bh[2], bh[3]);
            mma16816(acc[2 * np],     ah, bl[0], bl[1]);
            mma16816(acc[2 * np + 1], ah, bl[2], bl[3]);
        }
    }
}

// ---------------------------------------------------------------------------
// pre-kernel: build 9 weight images (transposed [n][k], hi/lo bf16, stride RS)
// ---------------------------------------------------------------------------
__global__ void convert_weights_kernel(const float* __restrict__ w1,
                                       const float* __restrict__ w2,
                                       const float* __restrict__ w3) {
    const int t = blockIdx.x * blockDim.x + threadIdx.x;  // 9*128*64 = 73728
    const int img = t >> 13;
    const int rem = t & 8191;
    const int n = rem >> 6;
    const int p = rem & 63;          // k-pair
    const float* src;
    if (img < 4)      src = w1 + img * (129 * 128);
    else if (img < 8) src = w2 + (img - 4) * (128 * 128);
    else              src = w3;
    const float v0 = src[(2 * p) * 128 + n];
    const float v1 = src[(2 * p + 1) * 128 + n];
    uint32_t hi, lo;
    pack_hilo(v0, v1, hi, lo);
    unsigned char* dst = g_wimg + img * IMG + n * RS + p * 4;
    *reinterpret_cast<uint32_t*>(dst)       = hi;
    *reinterpret_cast<uint32_t*>(dst + 256) = lo;
}

// ---------------------------------------------------------------------------
__global__ __launch_bounds__(THREADS, 2)
void fe_mma_kernel(const float* __restrict__ cont,   // [N,4]
                   const float* __restrict__ freqs,  // [4,64]
                   const float* __restrict__ w1,     // [4,129,128]
                   const float* __restrict__ b1,     // [4,128]
                   const float* __restrict__ ln1g,   // [4,128]
                   const float* __restrict__ ln1b,   // [4,128]
                   const float* __restrict__ b2,     // [4,128]
                   const float* __restrict__ outg,   // [128]
                   const float* __restrict__ outb,   // [128]
                   const float* __restrict__ b3,     // [128]
                   float* __restrict__ out)          // [N,128]
{
    extern __shared__ unsigned char smem[];
    const uint32_t sbase = smem_u32(smem);
    float2* red = reinterpret_cast<float2*>(smem + REDO);  // [2][64]

    const int tid  = threadIdx.x;
    const int lane = tid & 31;
    const int wid  = tid >> 5;
    const int wy = wid & 3, wx = wid >> 2;
    const int rg = wy * 16, nb = wx * 64;
    const int g = lane >> 2, m = lane & 3;
    const int r1 = rg + g, r2 = r1 + 8;
    const int row0 = blockIdx.x * TM;

    // ldmatrix per-lane base addresses (A: 16x16 x4-tile order; B: 2 n-tiles)
    const uint32_t aBase = sbase + SA
        + (uint32_t)(rg + (lane & 7) + 8 * ((lane >> 3) & 1)) * RS
        + (uint32_t)(lane >> 4) * 16u;
    const uint32_t bBase = sbase + SB
        + (uint32_t)(nb + (lane & 7) + 8 * (lane >> 4)) * RS
        + (uint32_t)((lane >> 3) & 1) * 16u;

    float accE[8][4];
#pragma unroll
    for (int i = 0; i < 8; ++i)
#pragma unroll
        for (int j = 0; j < 4; ++j) accE[i][j] = 0.0f;

    const int frow = tid >> 2;          // featgen: 4 threads per row
    const int fb   = (tid & 3) * 16;    // 16 freqs each

#pragma unroll 1
    for (int d = 0; d < 4; ++d) {
        __syncthreads();  // s_A/s_B reuse guard

        // stage w1[d] image
        {
            const unsigned char* src = g_wimg + d * IMG;
            for (int i = tid; i < IMG / 16; i += THREADS)
                cp_async16(sbase + SB + (uint32_t)i * 16u, src + i * 16);
            CP_COMMIT();
        }
        // featgen -> s_A (cos at k[0,64), sin at k[64,128), lo at +128 cols)
        {
            const float x = cont[(row0 + frow) * 4 + d];
            uint32_t chi[8], clo[8], shi[8], slo[8];
#pragma unroll
            for (int p = 0; p < 8; ++p) {
                const float f0 = freqs[d * 64 + fb + 2 * p];
                const float f1 = freqs[d * 64 + fb + 2 * p + 1];
                float c0, s0, c1, s1;
                __sincosf(x * f0 * 6.283185307179586477f, &s0, &c0);
                __sincosf(x * f1 * 6.283185307179586477f, &s1, &c1);
                pack_hilo(c0, c1, chi[p], clo[p]);
                pack_hilo(s0, s1, shi[p], slo[p]);
            }
            unsigned char* rowp = smem + SA + frow * RS;
            *reinterpret_cast<uint4*>(rowp + fb * 2)            = make_uint4(chi[0], chi[1], chi[2], chi[3]);
            *reinterpret_cast<uint4*>(rowp + fb * 2 + 16)       = make_uint4(chi[4], chi[5], chi[6], chi[7]);
            *reinterpret_cast<uint4*>(rowp + 128 + fb * 2)      = make_uint4(shi[0], shi[1], shi[2], shi[3]);
            *reinterpret_cast<uint4*>(rowp + 128 + fb * 2 + 16) = make_uint4(shi[4], shi[5], shi[6], shi[7]);
            *reinterpret_cast<uint4*>(rowp + 256 + fb * 2)      = make_uint4(clo[0], clo[1], clo[2], clo[3]);
            *reinterpret_cast<uint4*>(rowp + 256 + fb * 2 + 16) = make_uint4(clo[4], clo[5], clo[6], clo[7]);
            *reinterpret_cast<uint4*>(rowp + 384 + fb * 2)      = make_uint4(slo[0], slo[1], slo[2], slo[3]);
            *reinterpret_cast<uint4*>(rowp + 384 + fb * 2 + 16) = make_uint4(slo[4], slo[5], slo[6], slo[7]);
        }
        CP_WAIT0();
        __syncthreads();

        // ---- GEMM1 ----
        float acc[8][4];
#pragma unroll
        for (int i = 0; i < 8; ++i)
#pragma unroll
            for (int j = 0; j < 4; ++j) acc[i][j] = 0.0f;
        gemm_bf16x3(aBase, bBase, acc);
        __syncthreads();  // all reads of s_A/s_B done

        // stage w2[d] image (overlaps epilogue)
        {
            const unsigned char* src = g_wimg + (4 + d) * IMG;
            for (int i = tid; i < IMG / 16; i += THREADS)
                cp_async16(sbase + SB + (uint32_t)i * 16u, src + i * 16);
            CP_COMMIT();
        }
        // ---- epi1: + x*w1_last + b1, LN, ReLU -> s_A (bf16 hi/lo) ----
        {
            const float x1 = cont[(row0 + r1) * 4 + d];
            const float x2 = cont[(row0 + r2) * 4 + d];
            const float* w1l = w1 + d * (129 * 128) + 128 * 128;
            const float* b1d = b1 + d * 128;
            float v[8][4];
            float sum1 = 0.f, sq1 = 0.f, sum2 = 0.f, sq2 = 0.f;
#pragma unroll
            for (int nt = 0; nt < 8; ++nt) {
                const int c = nb + 8 * nt + 2 * m;
                const float wl0 = w1l[c], wl1 = w1l[c + 1];
                const float bb0 = b1d[c], bb1 = b1d[c + 1];
                const float v0 = acc[nt][0] + x1 * wl0 + bb0;
                const float v1 = acc[nt][1] + x1 * wl1 + bb1;
                const float v2 = acc[nt][2] + x2 * wl0 + bb0;
                const float v3 = acc[nt][3] + x2 * wl1 + bb1;
                v[nt][0] = v0; v[nt][1] = v1; v[nt][2] = v2; v[nt][3] = v3;
                sum1 += v0 + v1; sq1 += v0 * v0 + v1 * v1;
                sum2 += v2 + v3; sq2 += v2 * v2 + v3 * v3;
            }
#pragma unroll
            for (int msk = 1; msk <= 2; msk <<= 1) {
                sum1 += __shfl_xor_sync(0xffffffffu, sum1, msk);
                sq1  += __shfl_xor_sync(0xffffffffu, sq1,  msk);
                sum2 += __shfl_xor_sync(0xffffffffu, sum2, msk);
                sq2  += __shfl_xor_sync(0xffffffffu, sq2,  msk);
            }
            if (m == 0) {
                red[wx * 64 + r1] = make_float2(sum1, sq1);
                red[wx * 64 + r2] = make_float2(sum2, sq2);
            }
            __syncthreads();
            const float2 o1 = red[(1 - wx) * 64 + r1];
            const float2 o2 = red[(1 - wx) * 64 + r2];
            const float mu1 = (sum1 + o1.x) * (1.0f / 128.0f);
            const float mu2 = (sum2 + o2.x) * (1.0f / 128.0f);
            const float rs1 = rsqrtf((sq1 + o1.y) * (1.0f / 128.0f) - mu1 * mu1 + 1e-5f);
            const float rs2 = rsqrtf((sq2 + o2.y) * (1.0f / 128.0f) - mu2 * mu2 + 1e-5f);
            const float* gd = ln1g + d * 128;
            const float* bd = ln1b + d * 128;
#pragma unroll
            for (int nt = 0; nt < 8; ++nt) {
                const int c = nb + 8 * nt + 2 * m;
                const float g0 = gd[c], g1 = gd[c + 1];
                const float e0 = bd[c], e1 = bd[c + 1];
                const float h0 = fmaxf((v[nt][0] - mu1) * rs1 * g0 + e0, 0.f);
                const float h1 = fmaxf((v[nt][1] - mu1) * rs1 * g1 + e1, 0.f);
                const float h2 = fmaxf((v[nt][2] - mu2) * rs2 * g0 + e0, 0.f);
                const float h3 = fmaxf((v[nt][3] - mu2) * rs2 * g1 + e1, 0.f);
                uint32_t hi, lo;
                pack_hilo(h0, h1, hi, lo);
                *reinterpret_cast<uint32_t*>(smem + SA + r1 * RS + c * 2)       = hi;
                *reinterpret_cast<uint32_t*>(smem + SA + r1 * RS + 256 + c * 2) = lo;
                pack_hilo(h2, h3, hi, lo);
                *reinterpret_cast<uint32_t*>(smem + SA + r2 * RS + c * 2)       = hi;
                *reinterpret_cast<uint32_t*>(smem + SA + r2 * RS + 256 + c * 2) = lo;
            }
        }
        CP_WAIT0();
        __syncthreads();

        // ---- GEMM2 -> accE (accumulated over d) ----
        gemm_bf16x3(aBase, bBase, accE);
    }

    __syncthreads();
    // stage w3 image
    {
        const unsigned char* src = g_wimg + 8 * IMG;
        for (int i = tid; i < IMG / 16; i += THREADS)
            cp_async16(sbase + SB + (uint32_t)i * 16u, src + i * 16);
        CP_COMMIT();
    }
    // ---- epi2: + sum_d b2, LN(outg,outb), ReLU -> s_A ----
    {
        float v[8][4];
        float sum1 = 0.f, sq1 = 0.f, sum2 = 0.f, sq2 = 0.f;
#pragma unroll
        for (int nt = 0; nt < 8; ++nt) {
            const int c = nb + 8 * nt + 2 * m;
            const float bs0 = b2[c] + b2[128 + c] + b2[256 + c] + b2[384 + c];
            const float bs1 = b2[c + 1] + b2[128 + c + 1] + b2[256 + c + 1] + b2[384 + c + 1];
            const float v0 = accE[nt][0] + bs0;
            const float v1 = accE[nt][1] + bs1;
            const float v2 = accE[nt][2] + bs0;
            const float v3 = accE[nt][3] + bs1;
            v[nt][0] = v0; v[nt][1] = v1; v[nt][2] = v2; v[nt][3] = v3;
            sum1 += v0 + v1; sq1 += v0 * v0 + v1 * v1;
            sum2 += v2 + v3; sq2 += v2 * v2 + v3 * v3;
        }
#pragma unroll
        for (int msk = 1; msk <= 2; msk <<= 1) {
            sum1 += __shfl_xor_sync(0xffffffffu, sum1, msk);
            sq1  += __shfl_xor_sync(0xffffffffu, sq1,  msk);
            sum2 += __shfl_xor_sync(0xffffffffu, sum2, msk);
            sq2  += __shfl_xor_sync(0xffffffffu, sq2,  msk);
        }
        if (m == 0) {
            red[wx * 64 + r1] = make_float2(sum1, sq1);
            red[wx * 64 + r2] = make_float2(sum2, sq2);
        }
        __syncthreads();
        const float2 o1 = red[(1 - wx) * 64 + r1];
        const float2 o2 = red[(1 - wx) * 64 + r2];
        const float mu1 = (sum1 + o1.x) * (1.0f / 128.0f);
        const float mu2 = (sum2 + o2.x) * (1.0f / 128.0f);
        const float rs1 = rsqrtf((sq1 + o1.y) * (1.0f / 128.0f) - mu1 * mu1 + 1e-5f);
        const float rs2 = rsqrtf((sq2 + o2.y) * (1.0f / 128.0f) - mu2 * mu2 + 1e-5f);
#pragma unroll
        for (int nt = 0; nt < 8; ++nt) {
            const int c = nb + 8 * nt + 2 * m;
            const float g0 = outg[c], g1 = outg[c + 1];
            const float e0 = outb[c], e1 = outb[c + 1];
            const float h0 = fmaxf((v[nt][0] - mu1) * rs1 * g0 + e0, 0.f);
            const float h1 = fmaxf((v[nt][1] - mu1) * rs1 * g1 + e1, 0.f);
            const float h2 = fmaxf((v[nt][2] - mu2) * rs2 * g0 + e0, 0.f);
            const float h3 = fmaxf((v[nt][3] - mu2) * rs2 * g1 + e1, 0.f);
            uint32_t hi, lo;
            pack_hilo(h0, h1, hi, lo);
            *reinterpret_cast<uint32_t*>(smem + SA + r1 * RS + c * 2)       = hi;
            *reinterpret_cast<uint32_t*>(smem + SA + r1 * RS + 256 + c * 2) = lo;
            pack_hilo(h2, h3, hi, lo);
            *reinterpret_cast<uint32_t*>(smem + SA + r2 * RS + c * 2)       = hi;
            *reinterpret_cast<uint32_t*>(smem + SA + r2 * RS + 256 + c * 2) = lo;
        }
    }
    CP_WAIT0();
    __syncthreads();

    // ---- GEMM3 + b3 -> out ----
    float acc3[8][4];
#pragma unroll
    for (int i = 0; i < 8; ++i)
#pragma unroll
        for (int j = 0; j < 4; ++j) acc3[i][j] = 0.0f;
    gemm_bf16x3(aBase, bBase, acc3);

#pragma unroll
    for (int nt = 0; nt < 8; ++nt) {
        const int c = nb + 8 * nt + 2 * m;
        const float bb0 = b3[c], bb1 = b3[c + 1];
        *reinterpret_cast<float2*>(out + (size_t)(row0 + r1) * 128 + c) =
            make_float2(acc3[nt][0] + bb0, acc3[nt][1] + bb1);
        *reinterpret_cast<float2*>(out + (size_t)(row0 + r2) * 128 + c) =
            make_float2(acc3[nt][2] + bb0, acc3[nt][3] + bb1);
    }
}

// ---------------------------------------------------------------------------
extern "C" void kernel_launch(void* const* d_in, const int* in_sizes, int n_in,
                              void* d_out, int out_size)
{
    const float* cont  = (const float*)d_in[0];
    const float* freqs = (const float*)d_in[1];
    const float* w1    = (const float*)d_in[2];
    const float* b1    = (const float*)d_in[3];
    const float* ln1g  = (const float*)d_in[4];
    const float* ln1b  = (const float*)d_in[5];
    const float* w2    = (const float*)d_in[6];
    const float* b2    = (const float*)d_in[7];
    const float* outg  = (const float*)d_in[8];
    const float* outb  = (const float*)d_in[9];
    const float* w3    = (const float*)d_in[10];
    const float* b3    = (const float*)d_in[11];
    float* out = (float*)d_out;

    convert_weights_kernel<<<288, 256>>>(w1, w2, w3);

    cudaFuncSetAttribute(fe_mma_kernel,
                         cudaFuncAttributeMaxDynamicSharedMemorySize, SMEM_BYTES);
    fe_mma_kernel<<<NROWS / TM, THREADS, SMEM_BYTES>>>(
        cont, freqs, w1, b1, ln1g, ln1b, b2, outg, outb, b3, out);
}